// round 3
// baseline (speedup 1.0000x reference)
#include <cuda_runtime.h>
#include <cstdint>

// Problem constants
#define Bsz 256
#define Nn  512
#define Ff  256
#define Hh  256
#define NSTAGE 5
#define LN_EPS 1e-5f

// ---------------- scratch (device globals; no allocations allowed) ----------
__device__ float g_support[(size_t)Bsz * Nn * Hh];          // features @ W0
__device__ float g_xbuf[(size_t)Bsz * Nn * Hh];             // adj @ support + b0
__device__ unsigned long long g_amax[Bsz * NSTAGE];         // packed argmax keys
__device__ float g_zsum[Bsz * Hh];                          // sum over 5 pooled rows (post LN1/relu)

// ---------------- helpers ---------------------------------------------------
__device__ __forceinline__ unsigned int f2ord(float f) {
    unsigned int u = __float_as_uint(f);
    return (u & 0x80000000u) ? ~u : (u | 0x80000000u);
}

// block-wide sum for exactly 256 threads; sbuf must hold >= 8 floats
__device__ __forceinline__ float block_sum256(float v, float* sbuf) {
    #pragma unroll
    for (int o = 16; o > 0; o >>= 1) v += __shfl_xor_sync(0xffffffffu, v, o);
    if ((threadIdx.x & 31) == 0) sbuf[threadIdx.x >> 5] = v;
    __syncthreads();
    float t = 0.f;
    if (threadIdx.x < 32) {
        t = (threadIdx.x < 8) ? sbuf[threadIdx.x] : 0.f;
        #pragma unroll
        for (int o = 4; o > 0; o >>= 1) t += __shfl_xor_sync(0xffffffffu, t, o);
        if (threadIdx.x == 0) sbuf[0] = t;
    }
    __syncthreads();
    t = sbuf[0];
    __syncthreads();   // sbuf reusable after this
    return t;
}

// ---------------- init ------------------------------------------------------
__global__ void init_kernel() {
    int i = blockIdx.x * blockDim.x + threadIdx.x;
    if (i < Bsz * Hh) g_zsum[i] = 0.f;
    if (i < Bsz * NSTAGE) g_amax[i] = 0ull;
}

// ---------------- SGEMM 128x128x8, 256 threads, 8x8 per thread --------------
// C[z] = A[z](MxK,row) * B[z](KxN,row) (+ bias per col).  M%128==0, N%128==0, K%8==0.
#define BM 128
#define BN 128
#define BK 8
#define TM 8
#define TN 8

__global__ __launch_bounds__(256, 2)
void sgemm_kernel(const float* __restrict__ A, const float* __restrict__ B,
                  float* __restrict__ C, int M, int N, int K,
                  long long sA, long long sB, long long sC,
                  const float* __restrict__ bias) {
    A += (long long)blockIdx.z * sA;
    B += (long long)blockIdx.z * sB;
    C += (long long)blockIdx.z * sC;

    __shared__ float As[BK][BM];
    __shared__ float Bs[BK][BN];

    const int bx = blockIdx.x * BN;   // col offset
    const int by = blockIdx.y * BM;   // row offset
    const int tid = threadIdx.x;
    const int tx = tid & 15;          // 0..15  -> 8 cols each
    const int ty = tid >> 4;          // 0..15  -> 8 rows each

    // A tile load mapping: one float4 per thread
    const int arow = tid >> 1;            // 0..127
    const int acol = (tid & 1) * 4;       // 0 or 4
    // B tile load mapping: one float4 per thread
    const int brow = tid >> 5;            // 0..7
    const int bcol = (tid & 31) * 4;      // 0..124

    const float* Aptr = A + (long long)(by + arow) * K + acol;
    const float* Bptr = B + (long long)brow * N + bx + bcol;

    float acc[TM][TN];
    #pragma unroll
    for (int i = 0; i < TM; i++)
        #pragma unroll
        for (int j = 0; j < TN; j++) acc[i][j] = 0.f;

    for (int k0 = 0; k0 < K; k0 += BK) {
        float4 a4 = *(const float4*)(Aptr + k0);
        float4 b4 = *(const float4*)(Bptr + (long long)k0 * N);
        As[acol + 0][arow] = a4.x;
        As[acol + 1][arow] = a4.y;
        As[acol + 2][arow] = a4.z;
        As[acol + 3][arow] = a4.w;
        *(float4*)&Bs[brow][bcol] = b4;
        __syncthreads();

        #pragma unroll
        for (int kk = 0; kk < BK; kk++) {
            float ra[TM], rb[TN];
            #pragma unroll
            for (int i = 0; i < TM; i++) ra[i] = As[kk][ty * TM + i];
            #pragma unroll
            for (int j = 0; j < TN; j++) rb[j] = Bs[kk][tx * TN + j];
            #pragma unroll
            for (int i = 0; i < TM; i++)
                #pragma unroll
                for (int j = 0; j < TN; j++) acc[i][j] += ra[i] * rb[j];
        }
        __syncthreads();
    }

    // epilogue
    #pragma unroll
    for (int i = 0; i < TM; i++) {
        long long row = by + ty * TM + i;
        float* crow = C + row * N + bx + tx * TN;
        const float* bp = bias ? (bias + bx + tx * TN) : nullptr;
        #pragma unroll
        for (int j = 0; j < TN; j += 4) {
            float4 v;
            v.x = acc[i][j + 0];
            v.y = acc[i][j + 1];
            v.z = acc[i][j + 2];
            v.w = acc[i][j + 3];
            if (bp) {
                v.x += bp[j + 0]; v.y += bp[j + 1];
                v.z += bp[j + 2]; v.w += bp[j + 3];
            }
            *(float4*)(crow + j) = v;
        }
    }
}

// ---------------- layer-1 LN + relu + b1 -> score + per-stage argmax --------
// one block (256 thr) per (b,n) row of g_xbuf; nothing stored except argmax keys
__global__ __launch_bounds__(256)
void ln_score_kernel(const float* __restrict__ g0, const float* __restrict__ be0,
                     const float* __restrict__ b1, const int* __restrict__ stage_ids) {
    __shared__ float sbuf[8];
    const int row = blockIdx.x;          // b*Nn + n
    const int h = threadIdx.x;
    const float v = g_xbuf[(size_t)row * Hh + h];

    float mean = block_sum256(v, sbuf) * (1.f / Hh);
    float d = v - mean;
    float var = block_sum256(d * d, sbuf) * (1.f / Hh);
    float y = d * rsqrtf(var + LN_EPS) * g0[h] + be0[h];
    y = fmaxf(y, 0.f) + b1[h];           // == out[b,n,h]

    float score = block_sum256(y, sbuf);
    if (h == 0) {
        int b = row >> 9;                // / Nn
        unsigned int n = (unsigned int)(row & (Nn - 1));
        int s = stage_ids[row];
        unsigned long long key =
            ((unsigned long long)f2ord(score) << 32) |
            (unsigned long long)(0xFFFFFFFFu - n);   // lower index wins ties
        atomicMax(&g_amax[b * NSTAGE + s], key);
    }
}

// ---------------- gather winners, LN0(+b1) then LN1, accumulate zsum --------
// one block (256 thr) per (b, stage)
__global__ __launch_bounds__(256)
void pool_kernel(const float* __restrict__ g0, const float* __restrict__ be0,
                 const float* __restrict__ b1, const float* __restrict__ g1,
                 const float* __restrict__ be1) {
    __shared__ float sbuf[8];
    const int bs = blockIdx.x;
    const int b = bs / NSTAGE;
    const int h = threadIdx.x;

    unsigned long long key = g_amax[bs];
    unsigned int n = 0xFFFFFFFFu - (unsigned int)(key & 0xFFFFFFFFull);
    if (n >= Nn) n = 0;

    const float v = g_xbuf[((size_t)b * Nn + n) * Hh + h];

    // LN0 + relu + b1  (recompute "out" row)
    float mean = block_sum256(v, sbuf) * (1.f / Hh);
    float d = v - mean;
    float var = block_sum256(d * d, sbuf) * (1.f / Hh);
    float o = fmaxf(d * rsqrtf(var + LN_EPS) * g0[h] + be0[h], 0.f) + b1[h];

    // LN1 + relu
    float mean1 = block_sum256(o, sbuf) * (1.f / Hh);
    float d1 = o - mean1;
    float var1 = block_sum256(d1 * d1, sbuf) * (1.f / Hh);
    float z = fmaxf(d1 * rsqrtf(var1 + LN_EPS) * g1[h] + be1[h], 0.f);

    atomicAdd(&g_zsum[b * Hh + h], z);
}

// ---------------- layer 2 (row 0 only) + head -------------------------------
// one block (256 thr) per batch b
__global__ __launch_bounds__(256)
void final_kernel(const float* __restrict__ W2, const float* __restrict__ b2,
                  const float* __restrict__ g2, const float* __restrict__ be2,
                  const float* __restrict__ fcW, const float* __restrict__ fcb,
                  float* __restrict__ out) {
    __shared__ float zs[Hh];
    __shared__ float sbuf[8];
    const int b = blockIdx.x;
    const int h = threadIdx.x;

    zs[h] = g_zsum[b * Hh + h];
    __syncthreads();

    float acc = b2[h];
    #pragma unroll 8
    for (int k = 0; k < Hh; k++) acc += zs[k] * W2[k * Hh + h];

    float mean = block_sum256(acc, sbuf) * (1.f / Hh);
    float d = acc - mean;
    float var = block_sum256(d * d, sbuf) * (1.f / Hh);
    float y = fmaxf(d * rsqrtf(var + LN_EPS) * g2[h] + be2[h], 0.f);

    float p = block_sum256(y * fcW[h], sbuf);
    if (h == 0) out[b] = p + fcb[0];
}

// ---------------- launch -----------------------------------------------------
extern "C" void kernel_launch(void* const* d_in, const int* in_sizes, int n_in,
                              void* d_out, int out_size) {
    const float* adjacency = (const float*)d_in[0];
    const float* features  = (const float*)d_in[1];
    const int*   stage_ids = (const int*)  d_in[2];
    const float* W0  = (const float*)d_in[3];
    const float* b0  = (const float*)d_in[4];
    const float* b1  = (const float*)d_in[5];
    const float* W2  = (const float*)d_in[6];
    const float* b2  = (const float*)d_in[7];
    const float* g0  = (const float*)d_in[8];
    const float* be0 = (const float*)d_in[9];
    const float* g1  = (const float*)d_in[10];
    const float* be1 = (const float*)d_in[11];
    const float* g2  = (const float*)d_in[12];
    const float* be2 = (const float*)d_in[13];
    const float* fcW = (const float*)d_in[14];
    const float* fcb = (const float*)d_in[15];
    float* out = (float*)d_out;

    float* sup_ptr = nullptr;
    float* x_ptr = nullptr;
    cudaGetSymbolAddress((void**)&sup_ptr, g_support);
    cudaGetSymbolAddress((void**)&x_ptr, g_xbuf);

    // zero accumulators / argmax keys
    init_kernel<<<(Bsz * Hh + 255) / 256, 256>>>();

    // GEMM1: support = features @ W0   [B*N, F] x [F, H]
    {
        dim3 grid(Hh / BN, (Bsz * Nn) / BM, 1);
        sgemm_kernel<<<grid, 256>>>(features, W0, sup_ptr,
                                    Bsz * Nn, Hh, Ff, 0, 0, 0, nullptr);
    }

    // GEMM2 (batched): xbuf[b] = adjacency[b] @ support[b] + b0
    {
        dim3 grid(Hh / BN, Nn / BM, Bsz);
        sgemm_kernel<<<grid, 256>>>(adjacency, sup_ptr, x_ptr,
                                    Nn, Hh, Nn,
                                    (long long)Nn * Nn, (long long)Nn * Hh,
                                    (long long)Nn * Hh, b0);
    }

    // layer-1 LN/relu/+b1 -> per-node score -> per-(b,stage) argmax
    ln_score_kernel<<<Bsz * Nn, 256>>>(g0, be0, b1, stage_ids);

    // gather winners, recompute out rows, LN1+relu, accumulate zsum
    pool_kernel<<<Bsz * NSTAGE, 256>>>(g0, be0, b1, g1, be1);

    // layer 2 row 0 + head
    final_kernel<<<Bsz, 256>>>(W2, b2, g2, be2, fcW, fcb, out);
}